// round 4
// baseline (speedup 1.0000x reference)
#include <cuda_runtime.h>
#include <stdint.h>

typedef unsigned int u32;
typedef unsigned long long u64;
typedef unsigned char u8;

#define N_ANCH 262144
#define N_CLS  80
#define TOPK   1024
#define BND_CAP 4096
#define BINS   8192
#define KEY_LO 0xBF000000u
#define FULLM 0xFFFFFFFFu

// ---------------- scratch (static device globals; no allocation) ----------------
__device__ u32 g_key[N_ANCH];
__device__ u8  g_label[N_ANCH];
__device__ u32 g_hist[BINS];
__device__ u32 g_state[2];             // [0]=boundary bin B, [1]=A (count strictly above)
__device__ u32 g_cnt[2];               // [0]=above counter, [1]=boundary counter
__device__ u32 g_tick[4];              // last-block tickets (self-resetting)
__device__ u64 g_above[TOPK];
__device__ u64 g_bnd[BND_CAP];
__device__ u32 g_maxc;                 // float bits of max coord (coords >= 0)
__device__ float4 g_tbox[TOPK];
__device__ float  g_tconf[TOPK];
__device__ float  g_tlab[TOPK];
__device__ u32 g_sup[TOPK * TOPK / 32];
__device__ __align__(16) u8 g_rownz[TOPK];

__device__ __forceinline__ u32 key_bin(u32 k) {
    return (k >= KEY_LO) ? ((k - KEY_LO) >> 10) : 0u;   // < 8192
}

// ---------------- K1: argmax + 8192-bin hist + last-block scan ----------------
__global__ __launch_bounds__(256) void k1_argmax(const float* __restrict__ scores) {
    __shared__ u32 sh[BINS];
    __shared__ u32 suf[256];
    __shared__ u32 sLast;
    int t = threadIdx.x, lane = t & 31;
    for (int i = t; i < BINS; i += 256) sh[i] = 0u;
    __syncthreads();
    int gwarp = (blockIdx.x * 256 + t) >> 5;
    int nwarp = (gridDim.x * 256) >> 5;
    u32 runBin = FULLM, runCnt = 0;       // lane0 run-length aggregation
    for (int row = gwarp; row < N_ANCH; row += nwarp) {
        const float* r = scores + (size_t)row * N_CLS;
        float v = r[lane];
        int   c = lane;
        float v1 = r[32 + lane];
        if (v1 > v) { v = v1; c = lane + 32; }
        if (lane < 16) {
            float v2 = r[64 + lane];
            if (v2 > v) { v = v2; c = lane + 64; }
        }
        #pragma unroll
        for (int off = 16; off; off >>= 1) {
            float ov = __shfl_down_sync(FULLM, v, off);
            int   oc = __shfl_down_sync(FULLM, c, off);
            if (ov > v || (ov == v && oc < c)) { v = ov; c = oc; }
        }
        if (lane == 0) {
            float m = (v >= 0.5f) ? v : -1.0f;
            u32 b = __float_as_uint(m);
            u32 k = (b & 0x80000000u) ? ~b : (b | 0x80000000u);
            g_key[row]   = k;
            g_label[row] = (u8)c;
            u32 bin = key_bin(k);
            if (bin == runBin) runCnt++;
            else {
                if (runCnt) atomicAdd(&sh[runBin], runCnt);
                runBin = bin; runCnt = 1;
            }
        }
    }
    if (lane == 0 && runCnt) atomicAdd(&sh[runBin], runCnt);
    __syncthreads();
    for (int i = t; i < BINS; i += 256) if (sh[i]) atomicAdd(&g_hist[i], sh[i]);
    __threadfence();
    if (t == 0) sLast = (atomicAdd(&g_tick[0], 1u) == gridDim.x - 1) ? 1u : 0u;
    __syncthreads();
    if (!sLast) return;
    if (t == 0) g_tick[0] = 0u;
    // ---- scan: thread t owns bins [t*32, t*32+32); higher bin = higher key ----
    int base = t * 32;
    u32 tot = 0;
    #pragma unroll
    for (int q = 0; q < 32; q++) tot += g_hist[base + q];
    suf[t] = tot;
    __syncthreads();
    for (int off = 1; off < 256; off <<= 1) {
        u32 x = (t + off < 256) ? suf[t + off] : 0u;
        __syncthreads();
        suf[t] += x;
        __syncthreads();
    }
    u32 run = (t < 255) ? suf[t + 1] : 0u;    // count in bins strictly above this group
    for (int q = 31; q >= 0; q--) {
        u32 c = g_hist[base + q];
        u32 excl = run;
        u32 incl = run + c;
        if (excl < (u32)TOPK && incl >= (u32)TOPK) {
            g_state[0] = (u32)(base + q);
            g_state[1] = excl;
        }
        run = incl;
    }
    #pragma unroll
    for (int q = 0; q < 32; q++) g_hist[base + q] = 0u;   // self-clean
}

// ---------------- K2: gather above / boundary candidates (vectorized) ----------------
__global__ __launch_bounds__(256) void k2_gather() {
    int i4 = blockIdx.x * 256 + threadIdx.x;    // 65536 threads x 4 keys
    u32 B = g_state[0];
    uint4 kv = ((const uint4*)g_key)[i4];
    u32 ks[4] = {kv.x, kv.y, kv.z, kv.w};
    #pragma unroll
    for (int q = 0; q < 4; q++) {
        u32 k = ks[q];
        u32 bin = key_bin(k);
        if (bin < B) continue;
        u32 idx = (u32)(i4 * 4 + q);
        u64 key64 = ((u64)k << 32) | (u64)(FULLM - idx);
        if (bin > B) {
            u32 p = atomicAdd(&g_cnt[0], 1u);
            if (p < TOPK) g_above[p] = key64;
        } else {
            u32 p = atomicAdd(&g_cnt[1], 1u);
            if (p < BND_CAP) g_bnd[p] = key64;
        }
    }
}

// ---------------- K3: smem-staged ballot rank + scatter ----------------
#define AB_BLOCKS 16
#define BD_BLOCKS 48
__global__ __launch_bounds__(256) void k3_rank(const float4* __restrict__ boxes) {
    __shared__ u64 s[BND_CAP];               // 32KB
    int tid = threadIdx.x, wid = tid >> 5, lane = tid & 31;
    int b = blockIdx.x;
    u32 A  = min(g_cnt[0], (u32)TOPK);
    u32 nb = min(g_cnt[1], (u32)BND_CAP);
    const u64* list;
    u32 n, basepos, wg, NW;
    if (b < AB_BLOCKS) { list = g_above; n = A;  basepos = 0u; wg = b * 8 + wid;               NW = AB_BLOCKS * 8; }
    else               { list = g_bnd;   n = nb; basepos = A;  wg = (b - AB_BLOCKS) * 8 + wid; NW = BD_BLOCKS * 8; }
    for (u32 i = tid; i < n; i += 256) s[i] = list[i];
    __syncthreads();
    for (u32 me = wg; me < n; me += NW) {
        u64 myk = s[me];
        u32 rank = 0;
        for (u32 j0 = 0; j0 < n; j0 += 32) {
            u32 j = j0 + lane;
            u64 other = (j < n) ? s[j] : 0ull;
            rank += (u32)__popc(__ballot_sync(FULLM, other > myk));
        }
        u32 pos = basepos + rank;            // unique (idx tiebreak in low bits)
        if (pos < (u32)TOPK && lane == 0) {
            u32 key32 = (u32)(myk >> 32);
            u32 idx = FULLM - (u32)(myk & FULLM);
            u32 bits = (key32 & 0x80000000u) ? (key32 ^ 0x80000000u) : ~key32;
            float conf = __uint_as_float(bits);
            float4 bx = boxes[idx];
            g_tbox[pos]  = bx;
            g_tconf[pos] = conf;
            g_tlab[pos]  = (float)(int)g_label[idx];
            float mv = fmaxf(fmaxf(bx.x, bx.y), fmaxf(bx.z, bx.w));
            atomicMax(&g_maxc, __float_as_uint(mv));   // coords >= 0 -> bit-monotone
        }
    }
}

// ---------------- K4: offsets + IoU (ballot, conflict-free) + NMS + output ----------------
__global__ __launch_bounds__(256) void k4_iou_nms_out(float* __restrict__ out) {
    __shared__ float4 soff[TOPK];
    __shared__ float sarea[TOPK];
    __shared__ u32 skeep[32];
    __shared__ u32 sLast;
    int tid = threadIdx.x;  // 256
    float mc = __fadd_rn(__uint_as_float(g_maxc), 1.0f);
    for (int i = tid; i < TOPK; i += 256) {
        float4 bx = g_tbox[i];
        float tt = __fmul_rn(g_tlab[i], mc);
        float ox1 = __fadd_rn(bx.x, tt), oy1 = __fadd_rn(bx.y, tt);
        float ox2 = __fadd_rn(bx.z, tt), oy2 = __fadd_rn(bx.w, tt);
        soff[i]  = make_float4(ox1, oy1, ox2, oy2);
        sarea[i] = __fmul_rn(__fsub_rn(ox2, ox1), __fsub_rn(oy2, oy1));
    }
    __syncthreads();
    int wid = tid >> 5, lane = tid & 31;
    int i = blockIdx.x * 8 + wid;
    float4 bi = soff[i];
    float  ai = sarea[i];
    u32 myword = 0, nzrow = 0;
    #pragma unroll 8
    for (int jj = 0; jj < 32; jj++) {
        int j = jj * 32 + lane;                 // consecutive per lane: conflict-free
        float4 bj = soff[j];
        float lx = fmaxf(bi.x, bj.x), ly = fmaxf(bi.y, bj.y);
        float rx = fminf(bi.z, bj.z), ry = fminf(bi.w, bj.w);
        float wx = fmaxf(__fsub_rn(rx, lx), 0.0f);
        float wy = fmaxf(__fsub_rn(ry, ly), 0.0f);
        float inter = __fmul_rn(wx, wy);
        float un = __fsub_rn(__fadd_rn(ai, sarea[j]), inter);
        float iou = __fdiv_rn(inter, fmaxf(un, 1e-9f));
        u32 word = __ballot_sync(FULLM, (j > i) && (iou > 0.6f));
        if (lane == jj) myword = word;
        nzrow |= word;
    }
    g_sup[i * 32 + lane] = myword;              // coalesced
    if (lane == 0) g_rownz[i] = nzrow ? (u8)1 : (u8)0;
    __threadfence();
    if (tid == 0) sLast = (atomicAdd(&g_tick[1], 1u) == gridDim.x - 1) ? 1u : 0u;
    __syncthreads();
    if (!sLast) return;
    if (tid == 0) { g_tick[1] = 0u; g_cnt[0] = 0u; g_cnt[1] = 0u; g_maxc = 0u; } // self-clean
    // --- single-warp exact sequential greedy NMS (warp 0) ---
    if (tid < 32) {
        u32 kw = 0;
        #pragma unroll 8
        for (int j = 0; j < 32; j++)
            kw |= (g_tconf[tid * 32 + j] >= 0.5f) ? (1u << j) : 0u;
        u32 nz = 0;
        const u32* rp = (const u32*)g_rownz;
        #pragma unroll
        for (int q = 0; q < 8; q++) {
            u32 v = rp[tid * 8 + q];
            u32 bitsv = (v & 1u) | (((v >> 8) & 1u) << 1) |
                        (((v >> 16) & 1u) << 2) | (((v >> 24) & 1u) << 3);
            nz |= bitsv << (4 * q);
        }
        for (int g = 0; g < 32; g++) {
            u32 nzg = __shfl_sync(FULLM, nz, g);
            if (!nzg) continue;
            u32 kwg = __shfl_sync(FULLM, kw, g);
            u32 act = nzg & kwg;
            while (act) {
                int bb = __ffs(act) - 1;
                int r = g * 32 + bb;
                kw &= ~g_sup[r * 32 + tid];
                kwg = __shfl_sync(FULLM, kw, g);
                u32 maskAbove = (bb == 31) ? 0u : (FULLM << (bb + 1));
                act = nzg & kwg & maskAbove;
            }
        }
        skeep[tid] = kw;
    }
    __syncthreads();
    // --- output: 256 threads x 4 rows ---
    #pragma unroll
    for (int q = 0; q < 4; q++) {
        int k = tid * 4 + q;
        bool kp = (skeep[k >> 5] >> (k & 31)) & 1u;
        float2* o = (float2*)(out + (size_t)k * 6);
        if (kp) {
            float4 bx = g_tbox[k];
            o[0] = make_float2(bx.x, bx.y);
            o[1] = make_float2(bx.z, bx.w);
            o[2] = make_float2(g_tconf[k], g_tlab[k]);
        } else {
            float2 z = make_float2(0.f, 0.f);
            o[0] = z; o[1] = z; o[2] = z;
        }
    }
}

// ---------------- launch ----------------
extern "C" void kernel_launch(void* const* d_in, const int* in_sizes, int n_in,
                              void* d_out, int out_size) {
    const float* boxes  = (const float*)d_in[0];
    const float* scores = (const float*)d_in[1];
    if (in_sizes[0] != N_ANCH * 4) {  // defensive input-order check
        boxes  = (const float*)d_in[1];
        scores = (const float*)d_in[0];
    }
    float* out = (float*)d_out;

    k1_argmax<<<1184, 256>>>(scores);
    k2_gather<<<N_ANCH / 1024, 256>>>();
    k3_rank<<<AB_BLOCKS + BD_BLOCKS, 256>>>((const float4*)boxes);
    k4_iou_nms_out<<<TOPK / 8, 256>>>(out);
}